// round 3
// baseline (speedup 1.0000x reference)
#include <cuda_runtime.h>
#include <cstdint>

// Problem constants (from reference)
#define S_SCALE 64.0f
#define MARGIN  0.35f
#define BATCH   4096
#define NUM_CLASSES 50257u

// Total elements = 4096 * 50257 = 205,852,672 ; divisible by 4 -> exact float4 tiling.
#define N_TOTAL 205852672u
#define N_VEC4  (N_TOTAL / 4u)   // 51,463,168 ; 51,463,168 / 256 = 201,028 blocks exactly

// Fused kernel: stream in -> out with *S, subtracting M at (row, labels[row])
// inline. Each thread owns 4 consecutive elements (one float4). A chunk can
// straddle a row boundary (50257 % 4 != 0), so we track (row, col) across the
// 4 lanes and reload the label on wrap.
__global__ void __launch_bounds__(256) cosface_fused_kernel(
    const float4* __restrict__ in,
    const int*    __restrict__ labels,
    float4*       __restrict__ out)
{
    unsigned int i = blockIdx.x * 256u + threadIdx.x;
    if (i >= N_VEC4) return;

    float4 v = in[i];   // issue the load first; index math overlaps the miss

    unsigned int e   = i * 4u;
    unsigned int row = e / NUM_CLASSES;          // umulhi constant division
    unsigned int col = e - row * NUM_CLASSES;
    int lab = __ldg(labels + row);

    // lane 0
    if ((int)col == lab) v.x -= MARGIN;
    if (++col == NUM_CLASSES) { col = 0u; lab = __ldg(labels + row + 1u); }
    // lane 1
    if ((int)col == lab) v.y -= MARGIN;
    if (++col == NUM_CLASSES) { col = 0u; lab = __ldg(labels + row + 1u); }
    // lane 2
    if ((int)col == lab) v.z -= MARGIN;
    if (++col == NUM_CLASSES) { col = 0u; lab = __ldg(labels + row + 1u); }
    // lane 3
    if ((int)col == lab) v.w -= MARGIN;

    v.x *= S_SCALE;
    v.y *= S_SCALE;
    v.z *= S_SCALE;
    v.w *= S_SCALE;
    out[i] = v;
}

extern "C" void kernel_launch(void* const* d_in, const int* in_sizes, int n_in,
                              void* d_out, int out_size)
{
    const float* logits = (const float*)d_in[0];
    const int*   labels = (const int*)d_in[1];
    float*       out    = (float*)d_out;

    (void)in_sizes; (void)n_in; (void)out_size;

    dim3 grid((N_VEC4 + 255u) / 256u);   // 201,028 blocks, exact
    cosface_fused_kernel<<<grid, 256>>>((const float4*)logits, labels, (float4*)out);
}

// round 4
// speedup vs baseline: 1.1017x; 1.1017x over previous
#include <cuda_runtime.h>
#include <cstdint>

// Problem constants (from reference)
#define S_SCALE 64.0f
#define MARGIN  0.35f
#define BATCH   4096u
#define NUM_CLASSES 50257u

// Total elements = 4096 * 50257 = 205,852,672 ; divisible by 4 -> exact float4 tiling.
#define N_TOTAL 205852672u
#define N_VEC4  (N_TOTAL / 4u)   // 51,463,168 ; / 256 = 201,028 blocks exactly

// Fused streaming kernel with BLOCK-LEVEL label gating.
// Each block covers 1024 consecutive elements -> spans at most 2 rows.
// Thread 0 resolves the (<=2) label positions of those rows into global
// element indices p0/p1; all threads then do two cheap range compares.
__global__ void __launch_bounds__(256) cosface_fused2_kernel(
    const float4* __restrict__ in,
    const int*    __restrict__ labels,
    float4*       __restrict__ out)
{
    __shared__ unsigned int s_p0, s_p1;

    unsigned int i = blockIdx.x * 256u + threadIdx.x;
    float4 v = in[i];                       // main load issues immediately

    if (threadIdx.x == 0) {
        unsigned int e0   = blockIdx.x * 1024u;
        unsigned int eLast = e0 + 1023u;
        unsigned int r0 = e0 / NUM_CLASSES;
        unsigned int r1 = eLast / NUM_CLASSES;   // r1 == r0 or r0+1

        int lab0 = __ldg(labels + r0);
        unsigned int p0 = (lab0 >= 0) ? (r0 * NUM_CLASSES + (unsigned int)lab0)
                                      : 0xFFFFFFFFu;
        unsigned int p1 = p0;
        if (r1 != r0) {
            int lab1 = __ldg(labels + r1);
            p1 = (lab1 >= 0) ? (r1 * NUM_CLASSES + (unsigned int)lab1)
                             : 0xFFFFFFFFu;
        }
        s_p0 = p0;
        s_p1 = p1;
    }
    __syncthreads();

    unsigned int e  = i * 4u;
    unsigned int d0 = s_p0 - e;   // unsigned wrap: in-range iff < 4
    unsigned int d1 = s_p1 - e;

    if (d0 < 4u || d1 < 4u) {     // rare path: ~2 threads per block at most
        if (d0 == 0u || d1 == 0u) v.x -= MARGIN;
        if (d0 == 1u || d1 == 1u) v.y -= MARGIN;
        if (d0 == 2u || d1 == 2u) v.z -= MARGIN;
        if (d0 == 3u || d1 == 3u) v.w -= MARGIN;
    }

    v.x *= S_SCALE;
    v.y *= S_SCALE;
    v.z *= S_SCALE;
    v.w *= S_SCALE;
    out[i] = v;
}

extern "C" void kernel_launch(void* const* d_in, const int* in_sizes, int n_in,
                              void* d_out, int out_size)
{
    const float* logits = (const float*)d_in[0];
    const int*   labels = (const int*)d_in[1];
    float*       out    = (float*)d_out;

    (void)in_sizes; (void)n_in; (void)out_size;

    dim3 grid(N_VEC4 / 256u);   // 201,028 blocks, exact (N_VEC4 % 256 == 0)
    cosface_fused2_kernel<<<grid, 256>>>((const float4*)logits, labels, (float4*)out);
}